// round 6
// baseline (speedup 1.0000x reference)
#include <cuda_runtime.h>
#include <math.h>

// Problem constants (fixed by the reference generator)
#define DD 300
#define NMAX 100000
#define EMAX 200000

// ---------------- scratch (device globals; no allocation allowed) ----------
__device__ float g_e   [(size_t)EMAX * DD];   // edge features  [E,D]
__device__ float g_tmp [(size_t)EMAX * DD];   // Te; also t1 (first N*D) + hh (next N*D)
__device__ float g_h   [(size_t)NMAX * DD];   // node state h   [N,D]
__device__ float g_buf [(size_t)NMAX * DD];   // h + agg accumulator / addmat scratch
__device__ float g_stats[2 * DD];             // BN sum / sumsq

// ---------------- small elementwise kernels --------------------------------
__global__ void zero_stats_k() {
    int t = threadIdx.x;
    if (t < 2 * DD) g_stats[t] = 0.f;
}

__global__ void copy_k(const float* __restrict__ src, float* __restrict__ dst, long n) {
    long i = (long)blockIdx.x * blockDim.x + threadIdx.x;
    long stride = (long)gridDim.x * blockDim.x;
    for (; i < n; i += stride) dst[i] = src[i];
}

// Te[e,d] = relu(ea[e,0]*w1[0,d] + ea[e,1]*w1[1,d] + ea[e,2]*w1[2,d] + b1[d])
__global__ void edge_pre_k(const float* __restrict__ ea, const float* __restrict__ w1,
                           const float* __restrict__ b1, float* __restrict__ out, int E) {
    long idx = (long)blockIdx.x * blockDim.x + threadIdx.x;
    long total = (long)E * DD;
    if (idx >= total) return;
    int e = (int)(idx / DD), d = (int)(idx % DD);
    float v = ea[e*3+0]*w1[d] + ea[e*3+1]*w1[DD+d] + ea[e*3+2]*w1[2*DD+d] + b1[d];
    out[idx] = fmaxf(v, 0.f);
}

// t[i,d] = relu(ch[i]*w1[0,d] + fc[i]*w1[1,d] + b1[d]);  base[i,d] = emb[z[i],d]
__global__ void node_pre_k(const int* __restrict__ z, const float* __restrict__ ch,
                           const float* __restrict__ fc, const float* __restrict__ w1,
                           const float* __restrict__ b1, const float* __restrict__ emb,
                           float* __restrict__ t, float* __restrict__ base, int N) {
    long idx = (long)blockIdx.x * blockDim.x + threadIdx.x;
    long total = (long)N * DD;
    if (idx >= total) return;
    int i = (int)(idx / DD), d = (int)(idx % DD);
    float v = ch[i]*w1[d] + fc[i]*w1[DD+d] + b1[d];
    t[idx]    = fmaxf(v, 0.f);
    base[idx] = emb[(long)z[i]*DD + d];
}

// buf[dst] += relu(h[src] + e)  (one warp per edge)
__global__ void scatter_k(const float* __restrict__ h, const float* __restrict__ e,
                          const int* __restrict__ src, const int* __restrict__ dst,
                          float* __restrict__ buf, int E) {
    int warp = (int)(((long)blockIdx.x * blockDim.x + threadIdx.x) >> 5);
    int lane = threadIdx.x & 31;
    if (warp >= E) return;
    int s = src[warp], t = dst[warp];
    const float* hr = h + (long)s * DD;
    const float* er = e + (long)warp * DD;
    float* br = buf + (long)t * DD;
    #pragma unroll 4
    for (int d = lane; d < DD; d += 32) {
        float v = hr[d] + er[d];
        if (v > 0.f) atomicAdd(&br[d], v);
    }
}

// per-column sum / sumsq (coalesced: thread d reads column d of consecutive rows)
__global__ void bn_stats_k(const float* __restrict__ hh, int N) {
    int d = threadIdx.x;
    if (d >= DD) return;
    float s = 0.f, q = 0.f;
    for (int r = blockIdx.x; r < N; r += gridDim.x) {
        float v = hh[(long)r * DD + d];
        s += v; q += v * v;
    }
    atomicAdd(&g_stats[d], s);
    atomicAdd(&g_stats[DD + d], q);
}

// h = relu((hh - mu) * rstd * gamma + beta); also mirror into buf for next layer
__global__ void bn_apply_k(const float* __restrict__ hh, const float* __restrict__ gamma,
                           const float* __restrict__ beta, float* __restrict__ h,
                           float* __restrict__ buf, int N) {
    long idx = (long)blockIdx.x * blockDim.x + threadIdx.x;
    long total = (long)N * DD;
    if (idx >= total) return;
    int d = (int)(idx % DD);
    float invN = 1.f / (float)N;
    float mu  = g_stats[d] * invN;
    float var = g_stats[DD + d] * invN - mu * mu;
    float rstd = rsqrtf(var + 1e-5f);
    float v = (hh[idx] - mu) * rstd * gamma[d] + beta[d];
    v = fmaxf(v, 0.f);
    h[idx] = v;
    buf[idx] = v;
}

// ---------------- tiled fp32 GEMM: C = act(A[MxK] @ W[KxN] + bias [+ addmat]) ----
// BM=BN=128, BK=8, 256 threads, 8x8 micro-tile.
__global__ void sgemm_k(const float* __restrict__ A, const float* __restrict__ W,
                        const float* __restrict__ bias, const float* __restrict__ addmat,
                        float* __restrict__ C, int M, int N, int K, int doRelu) {
    __shared__ float As[8][128];
    __shared__ float Bs[8][132];
    int tid = threadIdx.x;
    int tx = tid & 15, ty = tid >> 4;
    int m0 = blockIdx.y * 128, n0 = blockIdx.x * 128;

    float acc[8][8];
    #pragma unroll
    for (int i = 0; i < 8; i++)
        #pragma unroll
        for (int j = 0; j < 8; j++) acc[i][j] = 0.f;

    int arow = tid >> 1, acol = (tid & 1) * 4;   // A tile: 128 rows x 8 k
    int brow = tid >> 5, bcol = (tid & 31) * 4;  // B tile: 8 k x 128 cols

    for (int k0 = 0; k0 < K; k0 += 8) {
        #pragma unroll
        for (int j = 0; j < 4; j++) {
            int kk = k0 + acol + j;
            int mm = m0 + arow;
            As[acol + j][arow] = (mm < M && kk < K) ? A[(long)mm * K + kk] : 0.f;
        }
        #pragma unroll
        for (int j = 0; j < 4; j++) {
            int nn = n0 + bcol + j;
            int kk = k0 + brow;
            Bs[brow][bcol + j] = (kk < K && nn < N) ? W[(long)kk * N + nn] : 0.f;
        }
        __syncthreads();
        #pragma unroll
        for (int kk = 0; kk < 8; kk++) {
            float a[8], b[8];
            #pragma unroll
            for (int i = 0; i < 8; i++) a[i] = As[kk][ty * 8 + i];
            #pragma unroll
            for (int j = 0; j < 8; j++) b[j] = Bs[kk][tx * 8 + j];
            #pragma unroll
            for (int i = 0; i < 8; i++)
                #pragma unroll
                for (int j = 0; j < 8; j++)
                    acc[i][j] = fmaf(a[i], b[j], acc[i][j]);
        }
        __syncthreads();
    }

    #pragma unroll
    for (int i = 0; i < 8; i++) {
        int m = m0 + ty * 8 + i;
        if (m >= M) continue;
        #pragma unroll
        for (int j = 0; j < 8; j++) {
            int n = n0 + tx * 8 + j;
            if (n >= N) continue;
            float v = acc[i][j] + bias[n];
            if (addmat) v += addmat[(long)m * N + n];
            if (doRelu) v = fmaxf(v, 0.f);
            C[(long)m * N + n] = v;
        }
    }
}

static void launch_sgemm(const float* A, const float* W, const float* b,
                         const float* addmat, float* C, int M, int N, int K, int relu) {
    dim3 grid((N + 127) / 128, (M + 127) / 128);
    sgemm_k<<<grid, 256>>>(A, W, b, addmat, C, M, N, K, relu);
}

// ---------------- driver ----------------------------------------------------
extern "C" void kernel_launch(void* const* d_in, const int* in_sizes, int n_in,
                              void* d_out, int out_size) {
    const int*   z    = (const int*)  d_in[0];
    const float* chir = (const float*)d_in[1];
    const float* fchg = (const float*)d_in[2];
    const int*   ei   = (const int*)  d_in[3];
    const float* ea   = (const float*)d_in[4];
    const float* emb  = (const float*)d_in[5];
    const float* nw1  = (const float*)d_in[6];
    const float* nb1  = (const float*)d_in[7];
    const float* nw2  = (const float*)d_in[8];
    const float* nb2  = (const float*)d_in[9];
    const float* ew1  = (const float*)d_in[10];
    const float* eb1  = (const float*)d_in[11];
    const float* ew2  = (const float*)d_in[12];
    const float* eb2  = (const float*)d_in[13];
    const float* gw1  = (const float*)d_in[14];
    const float* gb1  = (const float*)d_in[15];
    const float* gw2  = (const float*)d_in[16];
    const float* gb2  = (const float*)d_in[17];
    const float* gam  = (const float*)d_in[18];
    const float* bet  = (const float*)d_in[19];
    const float* ahw  = (const float*)d_in[20];
    const float* ahb  = (const float*)d_in[21];
    const float* chw  = (const float*)d_in[22];
    const float* chb  = (const float*)d_in[23];

    const int N = in_sizes[0];
    const int E = in_sizes[3] / 2;
    const int* src = ei;
    const int* dst = ei + E;

    float *pe, *ptmp, *ph, *pbuf;
    cudaGetSymbolAddress((void**)&pe,   g_e);
    cudaGetSymbolAddress((void**)&ptmp, g_tmp);
    cudaGetSymbolAddress((void**)&ph,   g_h);
    cudaGetSymbolAddress((void**)&pbuf, g_buf);

    const long ND = (long)N * DD;
    const long ED = (long)E * DD;
    float* pt1 = ptmp;        // [N,D]
    float* phh = ptmp + ND;   // [N,D]

    // ---- edge encoder: e = relu(ea @ ew1 + eb1) @ ew2 + eb2 ----
    edge_pre_k<<<(unsigned)((ED + 255) / 256), 256>>>(ea, ew1, eb1, ptmp, E);
    launch_sgemm(ptmp, ew2, eb2, nullptr, pe, E, DD, DD, 0);

    // ---- node init: h = emb[z] + relu(na @ nw1 + nb1) @ nw2 + nb2 ----
    node_pre_k<<<(unsigned)((ND + 255) / 256), 256>>>(z, chir, fchg, nw1, nb1, emb, pt1, pbuf, N);
    launch_sgemm(pt1, nw2, nb2, pbuf, ph, N, DD, DD, 0);

    // buf = h (base for layer-0 aggregation)
    copy_k<<<2048, 256>>>(ph, pbuf, ND);

    // ---- 5 GINE layers ----
    for (int l = 0; l < 5; l++) {
        // buf += relu(h[src] + e) scattered to dst
        scatter_k<<<(E + 7) / 8, 256>>>(ph, pe, src, dst, pbuf, E);
        // t1 = relu(buf @ W1 + b1)
        launch_sgemm(pbuf, gw1 + (long)l * DD * DD, gb1 + l * DD, nullptr, pt1, N, DD, DD, 1);
        // hh = t1 @ W2 + b2
        launch_sgemm(pt1, gw2 + (long)l * DD * DD, gb2 + l * DD, nullptr, phh, N, DD, DD, 0);
        // batchnorm (training stats) + relu; mirror into buf for next layer
        zero_stats_k<<<1, 2 * DD>>>();
        bn_stats_k<<<1184, 320>>>(phh, N);
        bn_apply_k<<<(unsigned)((ND + 255) / 256), 256>>>(phh, gam + l * DD, bet + l * DD, ph, pbuf, N);
    }

    // ---- heads ----
    float* out = (float*)d_out;
    launch_sgemm(ph, ahw, ahb, nullptr, out, N, 87, DD, 0);
    launch_sgemm(ph, chw, chb, nullptr, out + (long)N * 87, N, 6, DD, 0);
}

// round 7
// speedup vs baseline: 1.0000x; 1.0000x over previous
#include <cuda_runtime.h>
#include <math.h>

// Problem constants (fixed by the reference generator)
#define DD 300
#define NMAX 100000
#define EMAX 200000

// ---------------- scratch (device globals; no allocation allowed) ----------
__device__ float g_e   [(size_t)EMAX * DD];   // edge features  [E,D]
__device__ float g_tmp [(size_t)EMAX * DD];   // Te; also t1 (first N*D) + hh (next N*D)
__device__ float g_h   [(size_t)NMAX * DD];   // node state h   [N,D]
__device__ float g_buf [(size_t)NMAX * DD];   // h + agg accumulator / addmat scratch
__device__ float g_stats[2 * DD];             // BN sum / sumsq

// ---------------- small elementwise kernels --------------------------------
__global__ void zero_stats_k() {
    int t = threadIdx.x;
    if (t < 2 * DD) g_stats[t] = 0.f;
}

__global__ void copy_k(const float* __restrict__ src, float* __restrict__ dst, long n) {
    long i = (long)blockIdx.x * blockDim.x + threadIdx.x;
    long stride = (long)gridDim.x * blockDim.x;
    for (; i < n; i += stride) dst[i] = src[i];
}

// Te[e,d] = relu(ea[e,0]*w1[0,d] + ea[e,1]*w1[1,d] + ea[e,2]*w1[2,d] + b1[d])
__global__ void edge_pre_k(const float* __restrict__ ea, const float* __restrict__ w1,
                           const float* __restrict__ b1, float* __restrict__ out, int E) {
    long idx = (long)blockIdx.x * blockDim.x + threadIdx.x;
    long total = (long)E * DD;
    if (idx >= total) return;
    int e = (int)(idx / DD), d = (int)(idx % DD);
    float v = ea[e*3+0]*w1[d] + ea[e*3+1]*w1[DD+d] + ea[e*3+2]*w1[2*DD+d] + b1[d];
    out[idx] = fmaxf(v, 0.f);
}

// t[i,d] = relu(ch[i]*w1[0,d] + fc[i]*w1[1,d] + b1[d]);  base[i,d] = emb[z[i],d]
__global__ void node_pre_k(const int* __restrict__ z, const float* __restrict__ ch,
                           const float* __restrict__ fc, const float* __restrict__ w1,
                           const float* __restrict__ b1, const float* __restrict__ emb,
                           float* __restrict__ t, float* __restrict__ base, int N) {
    long idx = (long)blockIdx.x * blockDim.x + threadIdx.x;
    long total = (long)N * DD;
    if (idx >= total) return;
    int i = (int)(idx / DD), d = (int)(idx % DD);
    float v = ch[i]*w1[d] + fc[i]*w1[DD+d] + b1[d];
    t[idx]    = fmaxf(v, 0.f);
    base[idx] = emb[(long)z[i]*DD + d];
}

// buf[dst] += relu(h[src] + e)  (one warp per edge)
__global__ void scatter_k(const float* __restrict__ h, const float* __restrict__ e,
                          const int* __restrict__ src, const int* __restrict__ dst,
                          float* __restrict__ buf, int E) {
    int warp = (int)(((long)blockIdx.x * blockDim.x + threadIdx.x) >> 5);
    int lane = threadIdx.x & 31;
    if (warp >= E) return;
    int s = src[warp], t = dst[warp];
    const float* hr = h + (long)s * DD;
    const float* er = e + (long)warp * DD;
    float* br = buf + (long)t * DD;
    #pragma unroll 4
    for (int d = lane; d < DD; d += 32) {
        float v = hr[d] + er[d];
        if (v > 0.f) atomicAdd(&br[d], v);
    }
}

// per-column sum / sumsq (coalesced: thread d reads column d of consecutive rows)
__global__ void bn_stats_k(const float* __restrict__ hh, int N) {
    int d = threadIdx.x;
    if (d >= DD) return;
    float s = 0.f, q = 0.f;
    for (int r = blockIdx.x; r < N; r += gridDim.x) {
        float v = hh[(long)r * DD + d];
        s += v; q += v * v;
    }
    atomicAdd(&g_stats[d], s);
    atomicAdd(&g_stats[DD + d], q);
}

// h = relu((hh - mu) * rstd * gamma + beta); also mirror into buf for next layer
__global__ void bn_apply_k(const float* __restrict__ hh, const float* __restrict__ gamma,
                           const float* __restrict__ beta, float* __restrict__ h,
                           float* __restrict__ buf, int N) {
    long idx = (long)blockIdx.x * blockDim.x + threadIdx.x;
    long total = (long)N * DD;
    if (idx >= total) return;
    int d = (int)(idx % DD);
    float invN = 1.f / (float)N;
    float mu  = g_stats[d] * invN;
    float var = g_stats[DD + d] * invN - mu * mu;
    float rstd = rsqrtf(var + 1e-5f);
    float v = (hh[idx] - mu) * rstd * gamma[d] + beta[d];
    v = fmaxf(v, 0.f);
    h[idx] = v;
    buf[idx] = v;
}

// ---------------- tiled fp32 GEMM: C = act(A[MxK] @ W[KxN] + bias [+ addmat]) ----
// BM=BN=128, BK=8, 256 threads, 8x8 micro-tile.
__global__ void sgemm_k(const float* __restrict__ A, const float* __restrict__ W,
                        const float* __restrict__ bias, const float* __restrict__ addmat,
                        float* __restrict__ C, int M, int N, int K, int doRelu) {
    __shared__ float As[8][128];
    __shared__ float Bs[8][132];
    int tid = threadIdx.x;
    int tx = tid & 15, ty = tid >> 4;
    int m0 = blockIdx.y * 128, n0 = blockIdx.x * 128;

    float acc[8][8];
    #pragma unroll
    for (int i = 0; i < 8; i++)
        #pragma unroll
        for (int j = 0; j < 8; j++) acc[i][j] = 0.f;

    int arow = tid >> 1, acol = (tid & 1) * 4;   // A tile: 128 rows x 8 k
    int brow = tid >> 5, bcol = (tid & 31) * 4;  // B tile: 8 k x 128 cols

    for (int k0 = 0; k0 < K; k0 += 8) {
        #pragma unroll
        for (int j = 0; j < 4; j++) {
            int kk = k0 + acol + j;
            int mm = m0 + arow;
            As[acol + j][arow] = (mm < M && kk < K) ? A[(long)mm * K + kk] : 0.f;
        }
        #pragma unroll
        for (int j = 0; j < 4; j++) {
            int nn = n0 + bcol + j;
            int kk = k0 + brow;
            Bs[brow][bcol + j] = (kk < K && nn < N) ? W[(long)kk * N + nn] : 0.f;
        }
        __syncthreads();
        #pragma unroll
        for (int kk = 0; kk < 8; kk++) {
            float a[8], b[8];
            #pragma unroll
            for (int i = 0; i < 8; i++) a[i] = As[kk][ty * 8 + i];
            #pragma unroll
            for (int j = 0; j < 8; j++) b[j] = Bs[kk][tx * 8 + j];
            #pragma unroll
            for (int i = 0; i < 8; i++)
                #pragma unroll
                for (int j = 0; j < 8; j++)
                    acc[i][j] = fmaf(a[i], b[j], acc[i][j]);
        }
        __syncthreads();
    }

    #pragma unroll
    for (int i = 0; i < 8; i++) {
        int m = m0 + ty * 8 + i;
        if (m >= M) continue;
        #pragma unroll
        for (int j = 0; j < 8; j++) {
            int n = n0 + tx * 8 + j;
            if (n >= N) continue;
            float v = acc[i][j] + bias[n];
            if (addmat) v += addmat[(long)m * N + n];
            if (doRelu) v = fmaxf(v, 0.f);
            C[(long)m * N + n] = v;
        }
    }
}

static void launch_sgemm(const float* A, const float* W, const float* b,
                         const float* addmat, float* C, int M, int N, int K, int relu) {
    dim3 grid((N + 127) / 128, (M + 127) / 128);
    sgemm_k<<<grid, 256>>>(A, W, b, addmat, C, M, N, K, relu);
}

// ---------------- driver ----------------------------------------------------
extern "C" void kernel_launch(void* const* d_in, const int* in_sizes, int n_in,
                              void* d_out, int out_size) {
    const int*   z    = (const int*)  d_in[0];
    const float* chir = (const float*)d_in[1];
    const float* fchg = (const float*)d_in[2];
    const int*   ei   = (const int*)  d_in[3];
    const float* ea   = (const float*)d_in[4];
    const float* emb  = (const float*)d_in[5];
    const float* nw1  = (const float*)d_in[6];
    const float* nb1  = (const float*)d_in[7];
    const float* nw2  = (const float*)d_in[8];
    const float* nb2  = (const float*)d_in[9];
    const float* ew1  = (const float*)d_in[10];
    const float* eb1  = (const float*)d_in[11];
    const float* ew2  = (const float*)d_in[12];
    const float* eb2  = (const float*)d_in[13];
    const float* gw1  = (const float*)d_in[14];
    const float* gb1  = (const float*)d_in[15];
    const float* gw2  = (const float*)d_in[16];
    const float* gb2  = (const float*)d_in[17];
    const float* gam  = (const float*)d_in[18];
    const float* bet  = (const float*)d_in[19];
    const float* ahw  = (const float*)d_in[20];
    const float* ahb  = (const float*)d_in[21];
    const float* chw  = (const float*)d_in[22];
    const float* chb  = (const float*)d_in[23];

    const int N = in_sizes[0];
    const int E = in_sizes[3] / 2;
    const int* src = ei;
    const int* dst = ei + E;

    float *pe, *ptmp, *ph, *pbuf;
    cudaGetSymbolAddress((void**)&pe,   g_e);
    cudaGetSymbolAddress((void**)&ptmp, g_tmp);
    cudaGetSymbolAddress((void**)&ph,   g_h);
    cudaGetSymbolAddress((void**)&pbuf, g_buf);

    const long ND = (long)N * DD;
    const long ED = (long)E * DD;
    float* pt1 = ptmp;        // [N,D]
    float* phh = ptmp + ND;   // [N,D]

    // ---- edge encoder: e = relu(ea @ ew1 + eb1) @ ew2 + eb2 ----
    edge_pre_k<<<(unsigned)((ED + 255) / 256), 256>>>(ea, ew1, eb1, ptmp, E);
    launch_sgemm(ptmp, ew2, eb2, nullptr, pe, E, DD, DD, 0);

    // ---- node init: h = emb[z] + relu(na @ nw1 + nb1) @ nw2 + nb2 ----
    node_pre_k<<<(unsigned)((ND + 255) / 256), 256>>>(z, chir, fchg, nw1, nb1, emb, pt1, pbuf, N);
    launch_sgemm(pt1, nw2, nb2, pbuf, ph, N, DD, DD, 0);

    // buf = h (base for layer-0 aggregation)
    copy_k<<<2048, 256>>>(ph, pbuf, ND);

    // ---- 5 GINE layers ----
    for (int l = 0; l < 5; l++) {
        // buf += relu(h[src] + e) scattered to dst
        scatter_k<<<(E + 7) / 8, 256>>>(ph, pe, src, dst, pbuf, E);
        // t1 = relu(buf @ W1 + b1)
        launch_sgemm(pbuf, gw1 + (long)l * DD * DD, gb1 + l * DD, nullptr, pt1, N, DD, DD, 1);
        // hh = t1 @ W2 + b2
        launch_sgemm(pt1, gw2 + (long)l * DD * DD, gb2 + l * DD, nullptr, phh, N, DD, DD, 0);
        // batchnorm (training stats) + relu; mirror into buf for next layer
        zero_stats_k<<<1, 2 * DD>>>();
        bn_stats_k<<<1184, 320>>>(phh, N);
        bn_apply_k<<<(unsigned)((ND + 255) / 256), 256>>>(phh, gam + l * DD, bet + l * DD, ph, pbuf, N);
    }

    // ---- heads ----
    float* out = (float*)d_out;
    launch_sgemm(ph, ahw, ahb, nullptr, out, N, 87, DD, 0);
    launch_sgemm(ph, chw, chb, nullptr, out + (long)N * 87, N, 6, DD, 0);
}

// round 9
// speedup vs baseline: 1.2379x; 1.2379x over previous
#include <cuda_runtime.h>
#include <cuda_bf16.h>
#include <cstdint>
#include <math.h>

// Problem constants (fixed by the reference generator)
#define DD   300
#define KPAD 320          // K padded to 5 chunks of 64 bf16
#define NMAX 100000
#define EMAX 200000

// ---------------- scratch (device globals; no allocation allowed) ----------
__device__ float g_e   [(size_t)EMAX * DD];        // edge features  [E,D]
__device__ float g_tmp [(size_t)2 * NMAX * DD];    // t1 (first N*D) + hh (next N*D)
__device__ float g_h   [(size_t)NMAX * DD];        // node state h   [N,D]
__device__ float g_buf [(size_t)NMAX * DD];        // h + agg accumulator / addmat
__device__ float g_stats[2 * DD];                  // BN sum / sumsq
__device__ __nv_bfloat16 g_ahi[(size_t)EMAX * KPAD];  // activation hi split
__device__ __nv_bfloat16 g_alo[(size_t)EMAX * KPAD];  // activation lo split
__device__ __nv_bfloat16 g_whi[(size_t)DD * KPAD];    // weight^T hi split [n][k]
__device__ __nv_bfloat16 g_wlo[(size_t)DD * KPAD];    // weight^T lo split [n][k]

// ---------------- helpers ----------------------------------------------------
__device__ __forceinline__ uint32_t smem_u32(const void* p) {
    uint32_t a;
    asm("{ .reg .u64 t; cvta.to.shared.u64 t, %1; cvt.u32.u64 %0, t; }" : "=r"(a) : "l"(p));
    return a;
}
__device__ __forceinline__ void ldsm_x4(uint32_t* r, uint32_t addr) {
    asm volatile("ldmatrix.sync.aligned.m8n8.x4.shared.b16 {%0,%1,%2,%3}, [%4];"
                 : "=r"(r[0]), "=r"(r[1]), "=r"(r[2]), "=r"(r[3]) : "r"(addr));
}
__device__ __forceinline__ void mma_bf16(float* c, const uint32_t* a, const uint32_t* b) {
    asm volatile(
        "mma.sync.aligned.m16n8k16.row.col.f32.bf16.bf16.f32 "
        "{%0,%1,%2,%3}, {%4,%5,%6,%7}, {%8,%9}, {%0,%1,%2,%3};"
        : "+f"(c[0]), "+f"(c[1]), "+f"(c[2]), "+f"(c[3])
        : "r"(a[0]), "r"(a[1]), "r"(a[2]), "r"(a[3]), "r"(b[0]), "r"(b[1]));
}

// ---------------- split kernels ---------------------------------------------
// fp32 [M,DD] -> bf16 hi/lo [M,KPAD] (zero-padded K)
__global__ void split_k(const float* __restrict__ in,
                        __nv_bfloat16* __restrict__ hi, __nv_bfloat16* __restrict__ lo, int M) {
    long idx = (long)blockIdx.x * blockDim.x + threadIdx.x;
    if (idx >= (long)M * KPAD) return;
    int m = (int)(idx / KPAD), k = (int)(idx % KPAD);
    float x = (k < DD) ? in[(long)m * DD + k] : 0.f;
    __nv_bfloat16 h = __float2bfloat16(x);
    hi[idx] = h;
    lo[idx] = __float2bfloat16(x - __bfloat162float(h));
}

// W [K=DD, N=DD] fp32 -> transposed split [n][k] bf16 [DD, KPAD]
__global__ void wsplit_k(const float* __restrict__ W,
                         __nv_bfloat16* __restrict__ hi, __nv_bfloat16* __restrict__ lo) {
    int idx = blockIdx.x * blockDim.x + threadIdx.x;
    if (idx >= DD * KPAD) return;
    int n = idx / KPAD, k = idx % KPAD;
    float x = (k < DD) ? W[(long)k * DD + n] : 0.f;
    __nv_bfloat16 h = __float2bfloat16(x);
    hi[idx] = h;
    lo[idx] = __float2bfloat16(x - __bfloat162float(h));
}

// edge pre: relu(ea @ ew1 + eb1) -> split bf16 [E,KPAD]
__global__ void edge_pre_split_k(const float* __restrict__ ea, const float* __restrict__ w1,
                                 const float* __restrict__ b1,
                                 __nv_bfloat16* __restrict__ hi, __nv_bfloat16* __restrict__ lo, int E) {
    long idx = (long)blockIdx.x * blockDim.x + threadIdx.x;
    if (idx >= (long)E * KPAD) return;
    int e = (int)(idx / KPAD), d = (int)(idx % KPAD);
    float v = 0.f;
    if (d < DD) {
        v = ea[e*3+0]*w1[d] + ea[e*3+1]*w1[DD+d] + ea[e*3+2]*w1[2*DD+d] + b1[d];
        v = fmaxf(v, 0.f);
    }
    __nv_bfloat16 h = __float2bfloat16(v);
    hi[idx] = h;
    lo[idx] = __float2bfloat16(v - __bfloat162float(h));
}

// node pre: relu(na @ nw1 + nb1) -> split; base emb[z] -> pbuf
__global__ void node_pre_split_k(const int* __restrict__ z, const float* __restrict__ ch,
                                 const float* __restrict__ fc, const float* __restrict__ w1,
                                 const float* __restrict__ b1, const float* __restrict__ emb,
                                 __nv_bfloat16* __restrict__ hi, __nv_bfloat16* __restrict__ lo,
                                 float* __restrict__ base, int N) {
    long idx = (long)blockIdx.x * blockDim.x + threadIdx.x;
    if (idx >= (long)N * KPAD) return;
    int i = (int)(idx / KPAD), d = (int)(idx % KPAD);
    float v = 0.f;
    if (d < DD) {
        v = fmaxf(ch[i]*w1[d] + fc[i]*w1[DD+d] + b1[d], 0.f);
        base[(long)i * DD + d] = emb[(long)z[i] * DD + d];
    }
    __nv_bfloat16 h = __float2bfloat16(v);
    hi[idx] = h;
    lo[idx] = __float2bfloat16(v - __bfloat162float(h));
}

// ---------------- mma.sync bf16x3 GEMM ---------------------------------------
// C[M,Nout] = act((Ahi+Alo)[M,KPAD] @ ((Whi+Wlo)[Nout,KPAD])^T + bias [+ addmat])
// Block tile 128x64, K chunk 64 bf16; 8 warps (4m x 2n), warp tile 32x32.
#define BM 128
#define BN 64
#define TSTRIDE 144   // 128B data + 16B pad per smem row (conflict-free ldmatrix)
#define SA_H 0
#define SA_L (BM * TSTRIDE)
#define SB_H (2 * BM * TSTRIDE)
#define SB_L (2 * BM * TSTRIDE + BN * TSTRIDE)
#define SM_TOTAL (2 * BM * TSTRIDE + 2 * BN * TSTRIDE)   // 55296 bytes

__device__ __forceinline__ void stage_tile(const __nv_bfloat16* __restrict__ g,
                                           int row0, int rowMax, int kc,
                                           char* s, int tid, int rows) {
    int total = rows * 8;   // rows x 8 uint4 (64 bf16 per row)
    for (int i = tid; i < total; i += 256) {
        int row = i >> 3, u = i & 7;
        uint4 v = make_uint4(0u, 0u, 0u, 0u);
        int gr = row0 + row;
        if (gr < rowMax)
            v = *(const uint4*)(g + (long)gr * KPAD + kc + u * 8);
        *(uint4*)(s + row * TSTRIDE + u * 16) = v;
    }
}

__global__ void __launch_bounds__(256, 2)
mmagemm_k(const __nv_bfloat16* __restrict__ Ahi, const __nv_bfloat16* __restrict__ Alo,
          const __nv_bfloat16* __restrict__ Whi, const __nv_bfloat16* __restrict__ Wlo,
          const float* __restrict__ bias, const float* __restrict__ addmat,
          float* __restrict__ C, int M, int Nout, int doRelu) {
    extern __shared__ char sm[];
    const uint32_t sbase = smem_u32(sm);
    const int tid = threadIdx.x, wid = tid >> 5, lane = tid & 31;
    const int wm = wid & 3, wn = wid >> 2;               // 4 x 2 warp grid
    const int m0 = blockIdx.y * BM, n0 = blockIdx.x * BN;

    float acc[2][4][4];
    #pragma unroll
    for (int i = 0; i < 2; i++)
        #pragma unroll
        for (int j = 0; j < 4; j++)
            #pragma unroll
            for (int q = 0; q < 4; q++) acc[i][j][q] = 0.f;

    // ldmatrix lane addressing
    const int a_row  = lane & 15;             // A: row within 16
    const int a_kh   = lane >> 4;             // A: k-half (0/1)
    const int b_nin  = (lane & 7) + ((lane >> 4) << 3);  // B: n within 16
    const int b_kh   = (lane >> 3) & 1;       // B: k-half

    const uint32_t aBase = sbase + (uint32_t)((wm * 32 + a_row) * TSTRIDE + a_kh * 16);
    const uint32_t bBase = sbase + (uint32_t)((wn * 32 + b_nin) * TSTRIDE + b_kh * 16);

    for (int c = 0; c < 5; c++) {
        int kc = c * 64;
        stage_tile(Ahi, m0, M,    kc, sm + SA_H, tid, BM);
        stage_tile(Alo, m0, M,    kc, sm + SA_L, tid, BM);
        stage_tile(Whi, n0, Nout, kc, sm + SB_H, tid, BN);
        stage_tile(Wlo, n0, Nout, kc, sm + SB_L, tid, BN);
        __syncthreads();

        #pragma unroll
        for (int ks = 0; ks < 4; ks++) {
            uint32_t ah[2][4], al[2][4];
            #pragma unroll
            for (int i = 0; i < 2; i++) {
                ldsm_x4(ah[i], aBase + SA_H + i * (16 * TSTRIDE) + ks * 32);
                ldsm_x4(al[i], aBase + SA_L + i * (16 * TSTRIDE) + ks * 32);
            }
            uint32_t bh[4][2], bl[4][2];
            #pragma unroll
            for (int jj = 0; jj < 2; jj++) {
                uint32_t t[4];
                ldsm_x4(t, bBase + SB_H + jj * (16 * TSTRIDE) + ks * 32);
                bh[2*jj][0] = t[0]; bh[2*jj][1] = t[1];
                bh[2*jj+1][0] = t[2]; bh[2*jj+1][1] = t[3];
                ldsm_x4(t, bBase + SB_L + jj * (16 * TSTRIDE) + ks * 32);
                bl[2*jj][0] = t[0]; bl[2*jj][1] = t[1];
                bl[2*jj+1][0] = t[2]; bl[2*jj+1][1] = t[3];
            }
            #pragma unroll
            for (int i = 0; i < 2; i++)
                #pragma unroll
                for (int j = 0; j < 4; j++) {
                    mma_bf16(acc[i][j], ah[i], bh[j]);
                    mma_bf16(acc[i][j], ah[i], bl[j]);
                    mma_bf16(acc[i][j], al[i], bh[j]);
                }
        }
        __syncthreads();
    }

    // epilogue: direct stores with bias/addmat/relu
    const int g  = lane >> 2, tig = lane & 3;
    #pragma unroll
    for (int i = 0; i < 2; i++) {
        #pragma unroll
        for (int j = 0; j < 4; j++) {
            int row = m0 + wm * 32 + i * 16 + g;
            int col = n0 + wn * 32 + j * 8 + tig * 2;
            bool c0ok = (col < Nout), c1ok = (col + 1 < Nout);
            float b0 = c0ok ? bias[col] : 0.f;
            float b1 = c1ok ? bias[col + 1] : 0.f;
            #pragma unroll
            for (int half = 0; half < 2; half++) {
                int r = row + half * 8;
                if (r >= M) continue;
                float v0 = acc[i][j][half * 2 + 0] + b0;
                float v1 = acc[i][j][half * 2 + 1] + b1;
                if (addmat) {
                    if (c0ok) v0 += addmat[(long)r * Nout + col];
                    if (c1ok) v1 += addmat[(long)r * Nout + col + 1];
                }
                if (doRelu) { v0 = fmaxf(v0, 0.f); v1 = fmaxf(v1, 0.f); }
                if (c0ok) C[(long)r * Nout + col] = v0;
                if (c1ok) C[(long)r * Nout + col + 1] = v1;
            }
        }
    }
}

// ---------------- misc elementwise kernels ----------------------------------
__global__ void zero_stats_k() {
    int t = threadIdx.x;
    if (t < 2 * DD) g_stats[t] = 0.f;
}

__global__ void copy_k(const float* __restrict__ src, float* __restrict__ dst, long n) {
    long i = (long)blockIdx.x * blockDim.x + threadIdx.x;
    long stride = (long)gridDim.x * blockDim.x;
    for (; i < n; i += stride) dst[i] = src[i];
}

// buf[dst] += relu(h[src] + e)  (one warp per edge)
__global__ void scatter_k(const float* __restrict__ h, const float* __restrict__ e,
                          const int* __restrict__ src, const int* __restrict__ dst,
                          float* __restrict__ buf, int E) {
    int warp = (int)(((long)blockIdx.x * blockDim.x + threadIdx.x) >> 5);
    int lane = threadIdx.x & 31;
    if (warp >= E) return;
    int s = src[warp], t = dst[warp];
    const float* hr = h + (long)s * DD;
    const float* er = e + (long)warp * DD;
    float* br = buf + (long)t * DD;
    #pragma unroll 4
    for (int d = lane; d < DD; d += 32) {
        float v = hr[d] + er[d];
        if (v > 0.f) atomicAdd(&br[d], v);
    }
}

__global__ void bn_stats_k(const float* __restrict__ hh, int N) {
    int d = threadIdx.x;
    if (d >= DD) return;
    float s = 0.f, q = 0.f;
    for (int r = blockIdx.x; r < N; r += gridDim.x) {
        float v = hh[(long)r * DD + d];
        s += v; q += v * v;
    }
    atomicAdd(&g_stats[d], s);
    atomicAdd(&g_stats[DD + d], q);
}

__global__ void bn_apply_k(const float* __restrict__ hh, const float* __restrict__ gamma,
                           const float* __restrict__ beta, float* __restrict__ h,
                           float* __restrict__ buf, int N) {
    long idx = (long)blockIdx.x * blockDim.x + threadIdx.x;
    long total = (long)N * DD;
    if (idx >= total) return;
    int d = (int)(idx % DD);
    float invN = 1.f / (float)N;
    float mu  = g_stats[d] * invN;
    float var = g_stats[DD + d] * invN - mu * mu;
    float rstd = rsqrtf(var + 1e-5f);
    float v = (hh[idx] - mu) * rstd * gamma[d] + beta[d];
    v = fmaxf(v, 0.f);
    h[idx] = v;
    buf[idx] = v;
}

// ---------------- fp32 SGEMM (kept for skinny heads) ------------------------
__global__ void sgemm_k(const float* __restrict__ A, const float* __restrict__ W,
                        const float* __restrict__ bias, const float* __restrict__ addmat,
                        float* __restrict__ C, int M, int N, int K, int doRelu) {
    __shared__ float As[8][128];
    __shared__ float Bs[8][132];
    int tid = threadIdx.x;
    int tx = tid & 15, ty = tid >> 4;
    int m0 = blockIdx.y * 128, n0 = blockIdx.x * 128;

    float acc[8][8];
    #pragma unroll
    for (int i = 0; i < 8; i++)
        #pragma unroll
        for (int j = 0; j < 8; j++) acc[i][j] = 0.f;

    int arow = tid >> 1, acol = (tid & 1) * 4;
    int brow = tid >> 5, bcol = (tid & 31) * 4;

    for (int k0 = 0; k0 < K; k0 += 8) {
        #pragma unroll
        for (int j = 0; j < 4; j++) {
            int kk = k0 + acol + j;
            int mm = m0 + arow;
            As[acol + j][arow] = (mm < M && kk < K) ? A[(long)mm * K + kk] : 0.f;
        }
        #pragma unroll
        for (int j = 0; j < 4; j++) {
            int nn = n0 + bcol + j;
            int kk = k0 + brow;
            Bs[brow][bcol + j] = (kk < K && nn < N) ? W[(long)kk * N + nn] : 0.f;
        }
        __syncthreads();
        #pragma unroll
        for (int kk = 0; kk < 8; kk++) {
            float a[8], b[8];
            #pragma unroll
            for (int i = 0; i < 8; i++) a[i] = As[kk][ty * 8 + i];
            #pragma unroll
            for (int j = 0; j < 8; j++) b[j] = Bs[kk][tx * 8 + j];
            #pragma unroll
            for (int i = 0; i < 8; i++)
                #pragma unroll
                for (int j = 0; j < 8; j++)
                    acc[i][j] = fmaf(a[i], b[j], acc[i][j]);
        }
        __syncthreads();
    }

    #pragma unroll
    for (int i = 0; i < 8; i++) {
        int m = m0 + ty * 8 + i;
        if (m >= M) continue;
        #pragma unroll
        for (int j = 0; j < 8; j++) {
            int n = n0 + tx * 8 + j;
            if (n >= N) continue;
            float v = acc[i][j] + bias[n];
            if (addmat) v += addmat[(long)m * N + n];
            if (doRelu) v = fmaxf(v, 0.f);
            C[(long)m * N + n] = v;
        }
    }
}

static void launch_sgemm(const float* A, const float* W, const float* b,
                         const float* addmat, float* C, int M, int N, int K, int relu) {
    dim3 grid((N + 127) / 128, (M + 127) / 128);
    sgemm_k<<<grid, 256>>>(A, W, b, addmat, C, M, N, K, relu);
}

// ---------------- driver ----------------------------------------------------
static void launch_tcgemm(const __nv_bfloat16* ahi, const __nv_bfloat16* alo,
                          const __nv_bfloat16* whi, const __nv_bfloat16* wlo,
                          const float* bias, const float* addmat, float* C,
                          int M, int relu) {
    dim3 grid((DD + BN - 1) / BN, (M + BM - 1) / BM);
    mmagemm_k<<<grid, 256, SM_TOTAL>>>(ahi, alo, whi, wlo, bias, addmat, C, M, DD, relu);
}

extern "C" void kernel_launch(void* const* d_in, const int* in_sizes, int n_in,
                              void* d_out, int out_size) {
    const int*   z    = (const int*)  d_in[0];
    const float* chir = (const float*)d_in[1];
    const float* fchg = (const float*)d_in[2];
    const int*   ei   = (const int*)  d_in[3];
    const float* ea   = (const float*)d_in[4];
    const float* emb  = (const float*)d_in[5];
    const float* nw1  = (const float*)d_in[6];
    const float* nb1  = (const float*)d_in[7];
    const float* nw2  = (const float*)d_in[8];
    const float* nb2  = (const float*)d_in[9];
    const float* ew1  = (const float*)d_in[10];
    const float* eb1  = (const float*)d_in[11];
    const float* ew2  = (const float*)d_in[12];
    const float* eb2  = (const float*)d_in[13];
    const float* gw1  = (const float*)d_in[14];
    const float* gb1  = (const float*)d_in[15];
    const float* gw2  = (const float*)d_in[16];
    const float* gb2  = (const float*)d_in[17];
    const float* gam  = (const float*)d_in[18];
    const float* bet  = (const float*)d_in[19];
    const float* ahw  = (const float*)d_in[20];
    const float* ahb  = (const float*)d_in[21];
    const float* chw  = (const float*)d_in[22];
    const float* chb  = (const float*)d_in[23];

    const int N = in_sizes[0];
    const int E = in_sizes[3] / 2;
    const int* src = ei;
    const int* dst = ei + E;

    static int smem_set = 0;
    if (!smem_set) {
        cudaFuncSetAttribute(mmagemm_k, cudaFuncAttributeMaxDynamicSharedMemorySize, SM_TOTAL);
        smem_set = 1;
    }

    float *pe, *ptmp, *ph, *pbuf;
    __nv_bfloat16 *pahi, *palo, *pwhi, *pwlo;
    cudaGetSymbolAddress((void**)&pe,   g_e);
    cudaGetSymbolAddress((void**)&ptmp, g_tmp);
    cudaGetSymbolAddress((void**)&ph,   g_h);
    cudaGetSymbolAddress((void**)&pbuf, g_buf);
    cudaGetSymbolAddress((void**)&pahi, g_ahi);
    cudaGetSymbolAddress((void**)&palo, g_alo);
    cudaGetSymbolAddress((void**)&pwhi, g_whi);
    cudaGetSymbolAddress((void**)&pwlo, g_wlo);

    const long ND = (long)N * DD;
    float* pt1 = ptmp;        // [N,D]
    float* phh = ptmp + ND;   // [N,D]

    const int WS_BLK = (DD * KPAD + 255) / 256;

    // ---- edge encoder: e = relu(ea @ ew1 + eb1) @ ew2 + eb2 (bf16x3 tensor) ----
    edge_pre_split_k<<<(unsigned)(((long)E * KPAD + 255) / 256), 256>>>(ea, ew1, eb1, pahi, palo, E);
    wsplit_k<<<WS_BLK, 256>>>(ew2, pwhi, pwlo);
    launch_tcgemm(pahi, palo, pwhi, pwlo, eb2, nullptr, pe, E, 0);

    // ---- node init: h = emb[z] + relu(na @ nw1 + nb1) @ nw2 + nb2 ----
    node_pre_split_k<<<(unsigned)(((long)N * KPAD + 255) / 256), 256>>>(
        z, chir, fchg, nw1, nb1, emb, pahi, palo, pbuf, N);
    wsplit_k<<<WS_BLK, 256>>>(nw2, pwhi, pwlo);
    launch_tcgemm(pahi, palo, pwhi, pwlo, nb2, pbuf, ph, N, 0);

    // buf = h (base for layer-0 aggregation)
    copy_k<<<2048, 256>>>(ph, pbuf, ND);

    // ---- 5 GINE layers ----
    for (int l = 0; l < 5; l++) {
        scatter_k<<<(E + 7) / 8, 256>>>(ph, pe, src, dst, pbuf, E);
        // t1 = relu(buf @ W1 + b1)
        split_k<<<(unsigned)(((long)N * KPAD + 255) / 256), 256>>>(pbuf, pahi, palo, N);
        wsplit_k<<<WS_BLK, 256>>>(gw1 + (long)l * DD * DD, pwhi, pwlo);
        launch_tcgemm(pahi, palo, pwhi, pwlo, gb1 + l * DD, nullptr, pt1, N, 1);
        // hh = t1 @ W2 + b2
        split_k<<<(unsigned)(((long)N * KPAD + 255) / 256), 256>>>(pt1, pahi, palo, N);
        wsplit_k<<<WS_BLK, 256>>>(gw2 + (long)l * DD * DD, pwhi, pwlo);
        launch_tcgemm(pahi, palo, pwhi, pwlo, gb2 + l * DD, nullptr, phh, N, 0);
        // batchnorm (training stats) + relu; mirror into buf for next layer
        zero_stats_k<<<1, 2 * DD>>>();
        bn_stats_k<<<1184, 320>>>(phh, N);
        bn_apply_k<<<(unsigned)((ND + 255) / 256), 256>>>(phh, gam + l * DD, bet + l * DD, ph, pbuf, N);
    }

    // ---- heads (skinny N: keep fp32 SIMT) ----
    float* out = (float*)d_out;
    launch_sgemm(ph, ahw, ahb, nullptr, out, N, 87, DD, 0);
    launch_sgemm(ph, chw, chb, nullptr, out + (long)N * 87, N, 6, DD, 0);
}

// round 10
// speedup vs baseline: 2.0243x; 1.6353x over previous
#include <cuda_runtime.h>
#include <cuda_bf16.h>
#include <cstdint>
#include <math.h>

// Problem constants (fixed by the reference generator)
#define DD   300
#define KPAD 320          // K padded to 5 chunks of 64 bf16
#define NMAX 100000
#define EMAX 200000

// ---------------- scratch (device globals; no allocation allowed) ----------
__device__ float g_e   [(size_t)EMAX * DD];        // edge features  [E,D]
__device__ float g_tmp [(size_t)NMAX * DD];        // hh [N,D]
__device__ float g_h   [(size_t)NMAX * DD];        // node state h   [N,D]
__device__ float g_buf [(size_t)NMAX * DD];        // h + agg accumulator / addmat
__device__ float g_stats[2 * DD];                  // BN sum / sumsq
__device__ float g_hb[128];                        // concatenated head bias
__device__ __nv_bfloat16 g_ahi[(size_t)EMAX * KPAD];  // activation hi split (input A)
__device__ __nv_bfloat16 g_alo[(size_t)EMAX * KPAD];  // activation lo split
__device__ __nv_bfloat16 g_bhi[(size_t)NMAX * KPAD];  // split GEMM outputs (t1 / final h)
__device__ __nv_bfloat16 g_blo[(size_t)NMAX * KPAD];
__device__ __nv_bfloat16 g_whi[(size_t)DD * KPAD];    // weight^T hi split [n][k]
__device__ __nv_bfloat16 g_wlo[(size_t)DD * KPAD];    // weight^T lo split [n][k]

// ---------------- helpers ----------------------------------------------------
__device__ __forceinline__ uint32_t smem_u32(const void* p) {
    uint32_t a;
    asm("{ .reg .u64 t; cvta.to.shared.u64 t, %1; cvt.u32.u64 %0, t; }" : "=r"(a) : "l"(p));
    return a;
}
__device__ __forceinline__ void ldsm_x4(uint32_t* r, uint32_t addr) {
    asm volatile("ldmatrix.sync.aligned.m8n8.x4.shared.b16 {%0,%1,%2,%3}, [%4];"
                 : "=r"(r[0]), "=r"(r[1]), "=r"(r[2]), "=r"(r[3]) : "r"(addr));
}
__device__ __forceinline__ void mma_bf16(float* c, const uint32_t* a, const uint32_t* b) {
    asm volatile(
        "mma.sync.aligned.m16n8k16.row.col.f32.bf16.bf16.f32 "
        "{%0,%1,%2,%3}, {%4,%5,%6,%7}, {%8,%9}, {%0,%1,%2,%3};"
        : "+f"(c[0]), "+f"(c[1]), "+f"(c[2]), "+f"(c[3])
        : "r"(a[0]), "r"(a[1]), "r"(a[2]), "r"(a[3]), "r"(b[0]), "r"(b[1]));
}
__device__ __forceinline__ void cp16(uint32_t dst, const void* src, bool valid) {
    int sz = valid ? 16 : 0;
    asm volatile("cp.async.cg.shared.global [%0], [%1], 16, %2;"
                 :: "r"(dst), "l"(src), "r"(sz) : "memory");
}
__device__ __forceinline__ void cp_commit() {
    asm volatile("cp.async.commit_group;" ::: "memory");
}
template<int NWAIT> __device__ __forceinline__ void cp_wait() {
    asm volatile("cp.async.wait_group %0;" :: "n"(NWAIT) : "memory");
}

// ---------------- split kernels ---------------------------------------------
// fp32 [M,DD] -> bf16 hi/lo [M,KPAD] (zero-padded K)
__global__ void split_k(const float* __restrict__ in,
                        __nv_bfloat16* __restrict__ hi, __nv_bfloat16* __restrict__ lo, int M) {
    long idx = (long)blockIdx.x * blockDim.x + threadIdx.x;
    if (idx >= (long)M * KPAD) return;
    int m = (int)(idx / KPAD), k = (int)(idx % KPAD);
    float x = (k < DD) ? in[(long)m * DD + k] : 0.f;
    __nv_bfloat16 h = __float2bfloat16(x);
    hi[idx] = h;
    lo[idx] = __float2bfloat16(x - __bfloat162float(h));
}

// W [K=DD, N=DD] fp32 -> transposed split [n][k] bf16 [DD, KPAD]
__global__ void wsplit_k(const float* __restrict__ W,
                         __nv_bfloat16* __restrict__ hi, __nv_bfloat16* __restrict__ lo) {
    int idx = blockIdx.x * blockDim.x + threadIdx.x;
    if (idx >= DD * KPAD) return;
    int n = idx / KPAD, k = idx % KPAD;
    float x = (k < DD) ? W[(long)k * DD + n] : 0.f;
    __nv_bfloat16 h = __float2bfloat16(x);
    hi[idx] = h;
    lo[idx] = __float2bfloat16(x - __bfloat162float(h));
}

// heads: concat ahw [300,87] and chw [300,6] -> transposed split [93,KPAD]; fill g_hb
__global__ void hsplit_k(const float* __restrict__ ahw, const float* __restrict__ chw,
                         const float* __restrict__ ahb, const float* __restrict__ chb,
                         __nv_bfloat16* __restrict__ hi, __nv_bfloat16* __restrict__ lo) {
    int idx = blockIdx.x * blockDim.x + threadIdx.x;
    if (idx < 128) g_hb[idx] = (idx < 87) ? ahb[idx] : ((idx < 93) ? chb[idx - 87] : 0.f);
    if (idx >= 93 * KPAD) return;
    int n = idx / KPAD, k = idx % KPAD;
    float x = 0.f;
    if (k < DD) x = (n < 87) ? ahw[(long)k * 87 + n] : chw[(long)k * 6 + (n - 87)];
    __nv_bfloat16 h = __float2bfloat16(x);
    hi[idx] = h;
    lo[idx] = __float2bfloat16(x - __bfloat162float(h));
}

// edge pre: relu(ea @ ew1 + eb1) -> split bf16 [E,KPAD]
__global__ void edge_pre_split_k(const float* __restrict__ ea, const float* __restrict__ w1,
                                 const float* __restrict__ b1,
                                 __nv_bfloat16* __restrict__ hi, __nv_bfloat16* __restrict__ lo, int E) {
    long idx = (long)blockIdx.x * blockDim.x + threadIdx.x;
    if (idx >= (long)E * KPAD) return;
    int e = (int)(idx / KPAD), d = (int)(idx % KPAD);
    float v = 0.f;
    if (d < DD) {
        v = ea[e*3+0]*w1[d] + ea[e*3+1]*w1[DD+d] + ea[e*3+2]*w1[2*DD+d] + b1[d];
        v = fmaxf(v, 0.f);
    }
    __nv_bfloat16 h = __float2bfloat16(v);
    hi[idx] = h;
    lo[idx] = __float2bfloat16(v - __bfloat162float(h));
}

// node pre: relu(na @ nw1 + nb1) -> split; base emb[z] -> pbuf
__global__ void node_pre_split_k(const int* __restrict__ z, const float* __restrict__ ch,
                                 const float* __restrict__ fc, const float* __restrict__ w1,
                                 const float* __restrict__ b1, const float* __restrict__ emb,
                                 __nv_bfloat16* __restrict__ hi, __nv_bfloat16* __restrict__ lo,
                                 float* __restrict__ base, int N) {
    long idx = (long)blockIdx.x * blockDim.x + threadIdx.x;
    if (idx >= (long)N * KPAD) return;
    int i = (int)(idx / KPAD), d = (int)(idx % KPAD);
    float v = 0.f;
    if (d < DD) {
        v = fmaxf(ch[i]*w1[d] + fc[i]*w1[DD+d] + b1[d], 0.f);
        base[(long)i * DD + d] = emb[(long)z[i] * DD + d];
    }
    __nv_bfloat16 h = __float2bfloat16(v);
    hi[idx] = h;
    lo[idx] = __float2bfloat16(v - __bfloat162float(h));
}

// ---------------- mma.sync bf16x3 GEMM, cp.async double-buffered -------------
// Block tile 128x64, K chunk 64; 8 warps (4m x 2n), warp tile 32x32.
#define BM 128
#define BN 64
#define TSTRIDE 144   // 128B data + 16B pad per smem row (conflict-free ldmatrix)
#define ABYTES (BM * TSTRIDE)                 // 18432
#define BBYTES (BN * TSTRIDE)                 // 9216
#define OFF_AH 0
#define OFF_AL ABYTES
#define OFF_BH (2 * ABYTES)
#define OFF_BL (2 * ABYTES + BBYTES)
#define BUFSZ  (2 * ABYTES + 2 * BBYTES)      // 55296
#define SM_DBL (2 * BUFSZ)                    // 110592

// stage one hi/lo pair of tiles via cp.async (rows x 64 bf16, zero-fill OOB rows)
__device__ __forceinline__ void stage_pair(const __nv_bfloat16* __restrict__ hiP,
                                           const __nv_bfloat16* __restrict__ loP,
                                           int row0, int rowMax, int kc,
                                           uint32_t sH, uint32_t sL, int rows, int tid) {
    int total = rows * 8;   // rows x 8 x 16B
    for (int i = tid; i < total; i += 256) {
        int row = i >> 3, u = i & 7;
        int gr = row0 + row;
        bool valid = (gr < rowMax);
        long goff = (long)(valid ? gr : 0) * KPAD + kc + u * 8;
        uint32_t soff = (uint32_t)(row * TSTRIDE + u * 16);
        cp16(sH + soff, hiP + goff, valid);
        cp16(sL + soff, loP + goff, valid);
    }
}

__global__ void __launch_bounds__(256, 2)
mmagemm_k(const __nv_bfloat16* __restrict__ Ahi, const __nv_bfloat16* __restrict__ Alo,
          const __nv_bfloat16* __restrict__ Whi, const __nv_bfloat16* __restrict__ Wlo,
          const float* __restrict__ bias, const float* __restrict__ addmat,
          float* __restrict__ C, float* __restrict__ C2,
          __nv_bfloat16* __restrict__ Ohi, __nv_bfloat16* __restrict__ Olo,
          int M, int Nout, int doRelu) {
    extern __shared__ char sm[];
    const uint32_t sbase = smem_u32(sm);
    const int tid = threadIdx.x, wid = tid >> 5, lane = tid & 31;
    const int wm = wid & 3, wn = wid >> 2;               // 4 x 2 warp grid
    const int m0 = blockIdx.y * BM, n0 = blockIdx.x * BN;

    float acc[2][4][4];
    #pragma unroll
    for (int i = 0; i < 2; i++)
        #pragma unroll
        for (int j = 0; j < 4; j++)
            #pragma unroll
            for (int q = 0; q < 4; q++) acc[i][j][q] = 0.f;

    // ldmatrix lane addressing
    const int a_row  = lane & 15;
    const int a_kh   = lane >> 4;
    const int b_nin  = (lane & 7) + ((lane >> 4) << 3);
    const int b_kh   = (lane >> 3) & 1;
    const uint32_t aLane = (uint32_t)((wm * 32 + a_row) * TSTRIDE + a_kh * 16);
    const uint32_t bLane = (uint32_t)((wn * 32 + b_nin) * TSTRIDE + b_kh * 16);

    // prologue: stage chunk 0 into buffer 0
    stage_pair(Ahi, Alo, m0, M,    0, sbase + OFF_AH, sbase + OFF_AL, BM, tid);
    stage_pair(Whi, Wlo, n0, Nout, 0, sbase + OFF_BH, sbase + OFF_BL, BN, tid);
    cp_commit();

    #pragma unroll
    for (int c = 0; c < 5; c++) {
        if (c < 4) {
            uint32_t nb = sbase + (uint32_t)(((c + 1) & 1) * BUFSZ);
            int kc = (c + 1) * 64;
            stage_pair(Ahi, Alo, m0, M,    kc, nb + OFF_AH, nb + OFF_AL, BM, tid);
            stage_pair(Whi, Wlo, n0, Nout, kc, nb + OFF_BH, nb + OFF_BL, BN, tid);
            cp_commit();
            cp_wait<1>();
        } else {
            cp_wait<0>();
        }
        __syncthreads();

        const uint32_t base = sbase + (uint32_t)((c & 1) * BUFSZ);
        const uint32_t aB = base + aLane, bB = base + bLane;
        #pragma unroll
        for (int ks = 0; ks < 4; ks++) {
            uint32_t ah[2][4], al[2][4];
            #pragma unroll
            for (int i = 0; i < 2; i++) {
                ldsm_x4(ah[i], aB + OFF_AH + i * (16 * TSTRIDE) + ks * 32);
                ldsm_x4(al[i], aB + OFF_AL + i * (16 * TSTRIDE) + ks * 32);
            }
            uint32_t bh[4][2], bl[4][2];
            #pragma unroll
            for (int jj = 0; jj < 2; jj++) {
                uint32_t t[4];
                ldsm_x4(t, bB + OFF_BH + jj * (16 * TSTRIDE) + ks * 32);
                bh[2*jj][0] = t[0]; bh[2*jj][1] = t[1];
                bh[2*jj+1][0] = t[2]; bh[2*jj+1][1] = t[3];
                ldsm_x4(t, bB + OFF_BL + jj * (16 * TSTRIDE) + ks * 32);
                bl[2*jj][0] = t[0]; bl[2*jj][1] = t[1];
                bl[2*jj+1][0] = t[2]; bl[2*jj+1][1] = t[3];
            }
            #pragma unroll
            for (int i = 0; i < 2; i++)
                #pragma unroll
                for (int j = 0; j < 4; j++) {
                    mma_bf16(acc[i][j], ah[i], bh[j]);
                    mma_bf16(acc[i][j], ah[i], bl[j]);
                    mma_bf16(acc[i][j], al[i], bh[j]);
                }
        }
        __syncthreads();
    }

    // epilogue
    const int g  = lane >> 2, tig = lane & 3;
    #pragma unroll
    for (int i = 0; i < 2; i++) {
        #pragma unroll
        for (int j = 0; j < 4; j++) {
            int row = m0 + wm * 32 + i * 16 + g;
            int col = n0 + wn * 32 + j * 8 + tig * 2;
            #pragma unroll
            for (int half = 0; half < 2; half++) {
                int r = row + half * 8;
                if (r >= M) continue;
                #pragma unroll
                for (int q = 0; q < 2; q++) {
                    int cc = col + q;
                    if (cc >= Nout) continue;
                    float v = acc[i][j][half * 2 + q] + bias[cc];
                    if (addmat) v += addmat[(long)r * Nout + cc];
                    if (doRelu) v = fmaxf(v, 0.f);
                    if (Ohi) {
                        __nv_bfloat16 hv = __float2bfloat16(v);
                        Ohi[(long)r * KPAD + cc] = hv;
                        Olo[(long)r * KPAD + cc] = __float2bfloat16(v - __bfloat162float(hv));
                    } else if (C2) {
                        if (cc < 87) C[(long)r * 87 + cc];
                        if (cc < 87) C[(long)r * 87 + cc] = v;
                        else         C2[(long)r * 6 + (cc - 87)] = v;
                    } else {
                        C[(long)r * Nout + cc] = v;
                    }
                }
            }
        }
    }
}

// ---------------- misc elementwise kernels ----------------------------------
__global__ void zero_stats_k() {
    int t = threadIdx.x;
    if (t < 2 * DD) g_stats[t] = 0.f;
}

__global__ void copy_k(const float* __restrict__ src, float* __restrict__ dst, long n) {
    long i = (long)blockIdx.x * blockDim.x + threadIdx.x;
    long stride = (long)gridDim.x * blockDim.x;
    for (; i < n; i += stride) dst[i] = src[i];
}

// buf[dst] += relu(h[src] + e)  (one warp per edge)
__global__ void scatter_k(const float* __restrict__ h, const float* __restrict__ e,
                          const int* __restrict__ src, const int* __restrict__ dst,
                          float* __restrict__ buf, int E) {
    int warp = (int)(((long)blockIdx.x * blockDim.x + threadIdx.x) >> 5);
    int lane = threadIdx.x & 31;
    if (warp >= E) return;
    int s = src[warp], t = dst[warp];
    const float* hr = h + (long)s * DD;
    const float* er = e + (long)warp * DD;
    float* br = buf + (long)t * DD;
    #pragma unroll 4
    for (int d = lane; d < DD; d += 32) {
        float v = hr[d] + er[d];
        if (v > 0.f) atomicAdd(&br[d], v);
    }
}

__global__ void bn_stats_k(const float* __restrict__ hh, int N) {
    int d = threadIdx.x;
    if (d >= DD) return;
    float s = 0.f, q = 0.f;
    for (int r = blockIdx.x; r < N; r += gridDim.x) {
        float v = hh[(long)r * DD + d];
        s += v; q += v * v;
    }
    atomicAdd(&g_stats[d], s);
    atomicAdd(&g_stats[DD + d], q);
}

// h = relu(bn(hh)); mirror into buf; optional split output (final layer -> heads)
__global__ void bn_apply_k(const float* __restrict__ hh, const float* __restrict__ gamma,
                           const float* __restrict__ beta, float* __restrict__ h,
                           float* __restrict__ buf,
                           __nv_bfloat16* __restrict__ ohi, __nv_bfloat16* __restrict__ olo,
                           int N) {
    long idx = (long)blockIdx.x * blockDim.x + threadIdx.x;
    long total = (long)N * DD;
    if (idx >= total) return;
    int d = (int)(idx % DD);
    float invN = 1.f / (float)N;
    float mu  = g_stats[d] * invN;
    float var = g_stats[DD + d] * invN - mu * mu;
    float rstd = rsqrtf(var + 1e-5f);
    float v = (hh[idx] - mu) * rstd * gamma[d] + beta[d];
    v = fmaxf(v, 0.f);
    h[idx] = v;
    buf[idx] = v;
    if (ohi) {
        long r = idx / DD;
        __nv_bfloat16 hv = __float2bfloat16(v);
        ohi[r * KPAD + d] = hv;
        olo[r * KPAD + d] = __float2bfloat16(v - __bfloat162float(hv));
    }
}

// ---------------- driver ----------------------------------------------------
static void launch_mma(const __nv_bfloat16* ahi, const __nv_bfloat16* alo,
                       const __nv_bfloat16* whi, const __nv_bfloat16* wlo,
                       const float* bias, const float* addmat,
                       float* C, float* C2, __nv_bfloat16* ohi, __nv_bfloat16* olo,
                       int M, int Nout, int relu) {
    dim3 grid((Nout + BN - 1) / BN, (M + BM - 1) / BM);
    mmagemm_k<<<grid, 256, SM_DBL>>>(ahi, alo, whi, wlo, bias, addmat, C, C2, ohi, olo, M, Nout, relu);
}

extern "C" void kernel_launch(void* const* d_in, const int* in_sizes, int n_in,
                              void* d_out, int out_size) {
    const int*   z    = (const int*)  d_in[0];
    const float* chir = (const float*)d_in[1];
    const float* fchg = (const float*)d_in[2];
    const int*   ei   = (const int*)  d_in[3];
    const float* ea   = (const float*)d_in[4];
    const float* emb  = (const float*)d_in[5];
    const float* nw1  = (const float*)d_in[6];
    const float* nb1  = (const float*)d_in[7];
    const float* nw2  = (const float*)d_in[8];
    const float* nb2  = (const float*)d_in[9];
    const float* ew1  = (const float*)d_in[10];
    const float* eb1  = (const float*)d_in[11];
    const float* ew2  = (const float*)d_in[12];
    const float* eb2  = (const float*)d_in[13];
    const float* gw1  = (const float*)d_in[14];
    const float* gb1  = (const float*)d_in[15];
    const float* gw2  = (const float*)d_in[16];
    const float* gb2  = (const float*)d_in[17];
    const float* gam  = (const float*)d_in[18];
    const float* bet  = (const float*)d_in[19];
    const float* ahw  = (const float*)d_in[20];
    const float* ahb  = (const float*)d_in[21];
    const float* chw  = (const float*)d_in[22];
    const float* chb  = (const float*)d_in[23];

    const int N = in_sizes[0];
    const int E = in_sizes[3] / 2;
    const int* src = ei;
    const int* dst = ei + E;

    static int smem_set = 0;
    if (!smem_set) {
        cudaFuncSetAttribute(mmagemm_k, cudaFuncAttributeMaxDynamicSharedMemorySize, SM_DBL);
        smem_set = 1;
    }

    float *pe, *phh, *ph, *pbuf, *phb;
    __nv_bfloat16 *pahi, *palo, *pbhi, *pblo, *pwhi, *pwlo;
    cudaGetSymbolAddress((void**)&pe,   g_e);
    cudaGetSymbolAddress((void**)&phh,  g_tmp);
    cudaGetSymbolAddress((void**)&ph,   g_h);
    cudaGetSymbolAddress((void**)&pbuf, g_buf);
    cudaGetSymbolAddress((void**)&phb,  g_hb);
    cudaGetSymbolAddress((void**)&pahi, g_ahi);
    cudaGetSymbolAddress((void**)&palo, g_alo);
    cudaGetSymbolAddress((void**)&pbhi, g_bhi);
    cudaGetSymbolAddress((void**)&pblo, g_blo);
    cudaGetSymbolAddress((void**)&pwhi, g_whi);
    cudaGetSymbolAddress((void**)&pwlo, g_wlo);

    const long ND = (long)N * DD;
    const int WS_BLK = (DD * KPAD + 255) / 256;

    // ---- edge encoder: e = relu(ea @ ew1 + eb1) @ ew2 + eb2 ----
    edge_pre_split_k<<<(unsigned)(((long)E * KPAD + 255) / 256), 256>>>(ea, ew1, eb1, pahi, palo, E);
    wsplit_k<<<WS_BLK, 256>>>(ew2, pwhi, pwlo);
    launch_mma(pahi, palo, pwhi, pwlo, eb2, nullptr, pe, nullptr, nullptr, nullptr, E, DD, 0);

    // ---- node init: h = emb[z] + relu(na @ nw1 + nb1) @ nw2 + nb2 ----
    node_pre_split_k<<<(unsigned)(((long)N * KPAD + 255) / 256), 256>>>(
        z, chir, fchg, nw1, nb1, emb, pahi, palo, pbuf, N);
    wsplit_k<<<WS_BLK, 256>>>(nw2, pwhi, pwlo);
    launch_mma(pahi, palo, pwhi, pwlo, nb2, pbuf, ph, nullptr, nullptr, nullptr, N, DD, 0);

    // buf = h (base for layer-0 aggregation)
    copy_k<<<2048, 256>>>(ph, pbuf, ND);

    // ---- 5 GINE layers ----
    for (int l = 0; l < 5; l++) {
        scatter_k<<<(E + 7) / 8, 256>>>(ph, pe, src, dst, pbuf, E);
        // split(buf) -> A; GEMM1: t1 = relu(buf @ W1 + b1), split output -> bhi/blo
        split_k<<<(unsigned)(((long)N * KPAD + 255) / 256), 256>>>(pbuf, pahi, palo, N);
        wsplit_k<<<WS_BLK, 256>>>(gw1 + (long)l * DD * DD, pwhi, pwlo);
        launch_mma(pahi, palo, pwhi, pwlo, gb1 + l * DD, nullptr,
                   nullptr, nullptr, pbhi, pblo, N, DD, 1);
        // GEMM2: hh = t1 @ W2 + b2 (fp32 out for BN)
        wsplit_k<<<WS_BLK, 256>>>(gw2 + (long)l * DD * DD, pwhi, pwlo);
        launch_mma(pbhi, pblo, pwhi, pwlo, gb2 + l * DD, nullptr,
                   phh, nullptr, nullptr, nullptr, N, DD, 0);
        // batchnorm + relu; mirror into buf; final layer also emits split h for heads
        zero_stats_k<<<1, 2 * DD>>>();
        bn_stats_k<<<1184, 320>>>(phh, N);
        bool last = (l == 4);
        bn_apply_k<<<(unsigned)((ND + 255) / 256), 256>>>(
            phh, gam + l * DD, bet + l * DD, ph, pbuf,
            last ? pbhi : nullptr, last ? pblo : nullptr, N);
    }

    // ---- heads: one 93-col GEMM, epilogue routes to the two output regions ----
    float* out = (float*)d_out;
    hsplit_k<<<(93 * KPAD + 255) / 256, 256>>>(ahw, chw, ahb, chb, pwhi, pwlo);
    launch_mma(pbhi, pblo, pwhi, pwlo, phb, nullptr,
               out, out + (long)N * 87, nullptr, nullptr, N, 93, 0);
}

// round 11
// speedup vs baseline: 2.2296x; 1.1015x over previous
#include <cuda_runtime.h>
#include <cuda_bf16.h>
#include <cstdint>
#include <math.h>

// Problem constants (fixed by the reference generator)
#define DD   300
#define KPAD 320          // K padded to 5 chunks of 64 bf16
#define KP8  40           // KPAD/8  (uint4 groups of 8 bf16)
#define D4   75           // DD/4    (float4 groups)
#define NMAX 100000
#define EMAX 200000

// ---------------- scratch (device globals; no allocation allowed) ----------
__device__ float g_e   [(size_t)EMAX * DD];        // edge features  [E,D]
__device__ float g_tmp [(size_t)NMAX * DD];        // hh [N,D]
__device__ float g_h   [(size_t)NMAX * DD];        // node state h   [N,D]
__device__ float g_buf [(size_t)NMAX * DD];        // h + agg accumulator / addmat
__device__ float g_stats[2 * DD];                  // BN sum / sumsq
__device__ float g_hb[128];                        // concatenated head bias
__device__ __nv_bfloat16 g_ahi[(size_t)EMAX * KPAD];  // activation hi split (input A)
__device__ __nv_bfloat16 g_alo[(size_t)EMAX * KPAD];  // activation lo split
__device__ __nv_bfloat16 g_bhi[(size_t)NMAX * KPAD];  // split GEMM outputs (t1 / final h)
__device__ __nv_bfloat16 g_blo[(size_t)NMAX * KPAD];
__device__ __nv_bfloat16 g_whi[(size_t)DD * KPAD];    // weight^T hi split [n][k]
__device__ __nv_bfloat16 g_wlo[(size_t)DD * KPAD];    // weight^T lo split [n][k]

// ---------------- helpers ----------------------------------------------------
__device__ __forceinline__ uint32_t smem_u32(const void* p) {
    uint32_t a;
    asm("{ .reg .u64 t; cvta.to.shared.u64 t, %1; cvt.u32.u64 %0, t; }" : "=r"(a) : "l"(p));
    return a;
}
__device__ __forceinline__ void ldsm_x4(uint32_t* r, uint32_t addr) {
    asm volatile("ldmatrix.sync.aligned.m8n8.x4.shared.b16 {%0,%1,%2,%3}, [%4];"
                 : "=r"(r[0]), "=r"(r[1]), "=r"(r[2]), "=r"(r[3]) : "r"(addr));
}
__device__ __forceinline__ void mma_bf16(float* c, const uint32_t* a, const uint32_t* b) {
    asm volatile(
        "mma.sync.aligned.m16n8k16.row.col.f32.bf16.bf16.f32 "
        "{%0,%1,%2,%3}, {%4,%5,%6,%7}, {%8,%9}, {%0,%1,%2,%3};"
        : "+f"(c[0]), "+f"(c[1]), "+f"(c[2]), "+f"(c[3])
        : "r"(a[0]), "r"(a[1]), "r"(a[2]), "r"(a[3]), "r"(b[0]), "r"(b[1]));
}
__device__ __forceinline__ void cp16(uint32_t dst, const void* src, bool valid) {
    int sz = valid ? 16 : 0;
    asm volatile("cp.async.cg.shared.global [%0], [%1], 16, %2;"
                 :: "r"(dst), "l"(src), "r"(sz) : "memory");
}
__device__ __forceinline__ void cp_commit() {
    asm volatile("cp.async.commit_group;" ::: "memory");
}
template<int NWAIT> __device__ __forceinline__ void cp_wait() {
    asm volatile("cp.async.wait_group %0;" :: "n"(NWAIT) : "memory");
}
__device__ __forceinline__ unsigned pack_bf2(float a, float b) {
    unsigned lo = __bfloat16_as_ushort(__float2bfloat16(a));
    unsigned hi = __bfloat16_as_ushort(__float2bfloat16(b));
    return (hi << 16) | lo;
}
// split 8 fp32 values into hi/lo uint4 (8 bf16 each)
__device__ __forceinline__ void split8(const float* v, uint4& uh, uint4& ul) {
    float h[8], l[8];
    #pragma unroll
    for (int j = 0; j < 8; j++) {
        __nv_bfloat16 hb = __float2bfloat16(v[j]);
        h[j] = __bfloat162float(hb);
        l[j] = v[j] - h[j];
    }
    uh = make_uint4(pack_bf2(h[0], h[1]), pack_bf2(h[2], h[3]),
                    pack_bf2(h[4], h[5]), pack_bf2(h[6], h[7]));
    ul = make_uint4(pack_bf2(l[0], l[1]), pack_bf2(l[2], l[3]),
                    pack_bf2(l[4], l[5]), pack_bf2(l[6], l[7]));
}

// ---------------- split kernels (vectorized: 8 bf16 per thread) -------------
// fp32 [M,DD] -> bf16 hi/lo [M,KPAD]
__global__ void split_k(const float* __restrict__ in,
                        __nv_bfloat16* __restrict__ hi, __nv_bfloat16* __restrict__ lo, int M) {
    long idx = (long)blockIdx.x * blockDim.x + threadIdx.x;
    if (idx >= (long)M * KP8) return;
    long m = idx / KP8;
    int u = (int)(idx % KP8);
    const float4* in4 = (const float4*)(in) + m * D4;
    float v[8] = {0,0,0,0,0,0,0,0};
    int f0 = u * 2;
    if (f0 < D4)     { float4 a = in4[f0];     v[0]=a.x; v[1]=a.y; v[2]=a.z; v[3]=a.w; }
    if (f0 + 1 < D4) { float4 a = in4[f0 + 1]; v[4]=a.x; v[5]=a.y; v[6]=a.z; v[7]=a.w; }
    uint4 uh, ul;
    split8(v, uh, ul);
    ((uint4*)hi)[idx] = uh;
    ((uint4*)lo)[idx] = ul;
}

// W [K=DD, N=DD] fp32 -> transposed split [n][k] bf16 [DD, KPAD] (small; scalar ok)
__global__ void wsplit_k(const float* __restrict__ W,
                         __nv_bfloat16* __restrict__ hi, __nv_bfloat16* __restrict__ lo) {
    int idx = blockIdx.x * blockDim.x + threadIdx.x;
    if (idx >= DD * KPAD) return;
    int n = idx / KPAD, k = idx % KPAD;
    float x = (k < DD) ? W[(long)k * DD + n] : 0.f;
    __nv_bfloat16 h = __float2bfloat16(x);
    hi[idx] = h;
    lo[idx] = __float2bfloat16(x - __bfloat162float(h));
}

// heads: concat ahw [300,87] and chw [300,6] -> transposed split [93,KPAD]; fill g_hb
__global__ void hsplit_k(const float* __restrict__ ahw, const float* __restrict__ chw,
                         const float* __restrict__ ahb, const float* __restrict__ chb,
                         __nv_bfloat16* __restrict__ hi, __nv_bfloat16* __restrict__ lo) {
    int idx = blockIdx.x * blockDim.x + threadIdx.x;
    if (idx < 128) g_hb[idx] = (idx < 87) ? ahb[idx] : ((idx < 93) ? chb[idx - 87] : 0.f);
    if (idx >= 93 * KPAD) return;
    int n = idx / KPAD, k = idx % KPAD;
    float x = 0.f;
    if (k < DD) x = (n < 87) ? ahw[(long)k * 87 + n] : chw[(long)k * 6 + (n - 87)];
    __nv_bfloat16 h = __float2bfloat16(x);
    hi[idx] = h;
    lo[idx] = __float2bfloat16(x - __bfloat162float(h));
}

// edge pre: relu(ea @ ew1 + eb1) -> split bf16 [E,KPAD]  (8 outputs/thread)
__global__ void edge_pre_split_k(const float* __restrict__ ea, const float* __restrict__ w1,
                                 const float* __restrict__ b1,
                                 __nv_bfloat16* __restrict__ hi, __nv_bfloat16* __restrict__ lo, int E) {
    long idx = (long)blockIdx.x * blockDim.x + threadIdx.x;
    if (idx >= (long)E * KP8) return;
    long e = idx / KP8;
    int u = (int)(idx % KP8);
    float a0 = ea[e*3+0], a1 = ea[e*3+1], a2 = ea[e*3+2];
    float v[8];
    #pragma unroll
    for (int j = 0; j < 8; j++) {
        int k = u * 8 + j;
        float t = 0.f;
        if (k < DD)
            t = fmaxf(a0 * w1[k] + a1 * w1[DD + k] + a2 * w1[2*DD + k] + b1[k], 0.f);
        v[j] = t;
    }
    uint4 uh, ul;
    split8(v, uh, ul);
    ((uint4*)hi)[idx] = uh;
    ((uint4*)lo)[idx] = ul;
}

// node pre: relu(na @ nw1 + nb1) -> split; base emb[z] -> pbuf (float4 copies)
__global__ void node_pre_split_k(const int* __restrict__ z, const float* __restrict__ ch,
                                 const float* __restrict__ fc, const float* __restrict__ w1,
                                 const float* __restrict__ b1, const float* __restrict__ emb,
                                 __nv_bfloat16* __restrict__ hi, __nv_bfloat16* __restrict__ lo,
                                 float* __restrict__ base, int N) {
    long idx = (long)blockIdx.x * blockDim.x + threadIdx.x;
    if (idx >= (long)N * KP8) return;
    long i = idx / KP8;
    int u = (int)(idx % KP8);
    float c0 = ch[i], f0 = fc[i];
    float v[8];
    #pragma unroll
    for (int j = 0; j < 8; j++) {
        int k = u * 8 + j;
        v[j] = (k < DD) ? fmaxf(c0 * w1[k] + f0 * w1[DD + k] + b1[k], 0.f) : 0.f;
    }
    uint4 uh, ul;
    split8(v, uh, ul);
    ((uint4*)hi)[idx] = uh;
    ((uint4*)lo)[idx] = ul;
    // base = emb[z[i]] (float4 copy of this thread's 8-float span)
    const float4* er = (const float4*)(emb) + (long)z[i] * D4;
    float4* br = (float4*)(base) + i * D4;
    int g0 = u * 2;
    if (g0 < D4)     br[g0]     = er[g0];
    if (g0 + 1 < D4) br[g0 + 1] = er[g0 + 1];
}

// ---------------- mma.sync bf16x3 GEMM, cp.async double-buffered -------------
#define BM 128
#define BN 64
#define TSTRIDE 144
#define ABYTES (BM * TSTRIDE)
#define BBYTES (BN * TSTRIDE)
#define OFF_AH 0
#define OFF_AL ABYTES
#define OFF_BH (2 * ABYTES)
#define OFF_BL (2 * ABYTES + BBYTES)
#define BUFSZ  (2 * ABYTES + 2 * BBYTES)
#define SM_DBL (2 * BUFSZ)

__device__ __forceinline__ void stage_pair(const __nv_bfloat16* __restrict__ hiP,
                                           const __nv_bfloat16* __restrict__ loP,
                                           int row0, int rowMax, int kc,
                                           uint32_t sH, uint32_t sL, int rows, int tid) {
    int total = rows * 8;
    for (int i = tid; i < total; i += 256) {
        int row = i >> 3, u = i & 7;
        int gr = row0 + row;
        bool valid = (gr < rowMax);
        long goff = (long)(valid ? gr : 0) * KPAD + kc + u * 8;
        uint32_t soff = (uint32_t)(row * TSTRIDE + u * 16);
        cp16(sH + soff, hiP + goff, valid);
        cp16(sL + soff, loP + goff, valid);
    }
}

__global__ void __launch_bounds__(256, 2)
mmagemm_k(const __nv_bfloat16* __restrict__ Ahi, const __nv_bfloat16* __restrict__ Alo,
          const __nv_bfloat16* __restrict__ Whi, const __nv_bfloat16* __restrict__ Wlo,
          const float* __restrict__ bias, const float* __restrict__ addmat,
          float* __restrict__ C, float* __restrict__ C2, float* __restrict__ Cmir,
          __nv_bfloat16* __restrict__ Ohi, __nv_bfloat16* __restrict__ Olo,
          int M, int Nout, int doRelu, int doStats) {
    extern __shared__ char sm[];
    const uint32_t sbase = smem_u32(sm);
    const int tid = threadIdx.x, wid = tid >> 5, lane = tid & 31;
    const int wm = wid & 3, wn = wid >> 2;
    const int m0 = blockIdx.y * BM, n0 = blockIdx.x * BN;

    float acc[2][4][4];
    #pragma unroll
    for (int i = 0; i < 2; i++)
        #pragma unroll
        for (int j = 0; j < 4; j++)
            #pragma unroll
            for (int q = 0; q < 4; q++) acc[i][j][q] = 0.f;

    const int a_row = lane & 15;
    const int a_kh  = lane >> 4;
    const int b_nin = (lane & 7) + ((lane >> 4) << 3);
    const int b_kh  = (lane >> 3) & 1;
    const uint32_t aLane = (uint32_t)((wm * 32 + a_row) * TSTRIDE + a_kh * 16);
    const uint32_t bLane = (uint32_t)((wn * 32 + b_nin) * TSTRIDE + b_kh * 16);

    stage_pair(Ahi, Alo, m0, M,    0, sbase + OFF_AH, sbase + OFF_AL, BM, tid);
    stage_pair(Whi, Wlo, n0, Nout, 0, sbase + OFF_BH, sbase + OFF_BL, BN, tid);
    cp_commit();

    #pragma unroll
    for (int c = 0; c < 5; c++) {
        if (c < 4) {
            uint32_t nb = sbase + (uint32_t)(((c + 1) & 1) * BUFSZ);
            int kc = (c + 1) * 64;
            stage_pair(Ahi, Alo, m0, M,    kc, nb + OFF_AH, nb + OFF_AL, BM, tid);
            stage_pair(Whi, Wlo, n0, Nout, kc, nb + OFF_BH, nb + OFF_BL, BN, tid);
            cp_commit();
            cp_wait<1>();
        } else {
            cp_wait<0>();
        }
        __syncthreads();

        const uint32_t base = sbase + (uint32_t)((c & 1) * BUFSZ);
        const uint32_t aB = base + aLane, bB = base + bLane;
        #pragma unroll
        for (int ks = 0; ks < 4; ks++) {
            uint32_t ah[2][4], al[2][4];
            #pragma unroll
            for (int i = 0; i < 2; i++) {
                ldsm_x4(ah[i], aB + OFF_AH + i * (16 * TSTRIDE) + ks * 32);
                ldsm_x4(al[i], aB + OFF_AL + i * (16 * TSTRIDE) + ks * 32);
            }
            uint32_t bh[4][2], bl[4][2];
            #pragma unroll
            for (int jj = 0; jj < 2; jj++) {
                uint32_t t[4];
                ldsm_x4(t, bB + OFF_BH + jj * (16 * TSTRIDE) + ks * 32);
                bh[2*jj][0] = t[0]; bh[2*jj][1] = t[1];
                bh[2*jj+1][0] = t[2]; bh[2*jj+1][1] = t[3];
                ldsm_x4(t, bB + OFF_BL + jj * (16 * TSTRIDE) + ks * 32);
                bl[2*jj][0] = t[0]; bl[2*jj][1] = t[1];
                bl[2*jj+1][0] = t[2]; bl[2*jj+1][1] = t[3];
            }
            #pragma unroll
            for (int i = 0; i < 2; i++)
                #pragma unroll
                for (int j = 0; j < 4; j++) {
                    mma_bf16(acc[i][j], ah[i], bh[j]);
                    mma_bf16(acc[i][j], ah[i], bl[j]);
                    mma_bf16(acc[i][j], al[i], bh[j]);
                }
        }
        __syncthreads();
    }

    // epilogue (+ optional per-column BN statistics)
    const int g  = lane >> 2, tig = lane & 3;
    float cs[8], cq[8];
    #pragma unroll
    for (int t = 0; t < 8; t++) { cs[t] = 0.f; cq[t] = 0.f; }

    #pragma unroll
    for (int i = 0; i < 2; i++) {
        #pragma unroll
        for (int j = 0; j < 4; j++) {
            int row = m0 + wm * 32 + i * 16 + g;
            int col = n0 + wn * 32 + j * 8 + tig * 2;
            #pragma unroll
            for (int half = 0; half < 2; half++) {
                int r = row + half * 8;
                if (r >= M) continue;
                #pragma unroll
                for (int q = 0; q < 2; q++) {
                    int cc = col + q;
                    if (cc >= Nout) continue;
                    float v = acc[i][j][half * 2 + q] + bias[cc];
                    if (addmat) v += addmat[(long)r * Nout + cc];
                    if (doRelu) v = fmaxf(v, 0.f);
                    if (doStats) { cs[j*2+q] += v; cq[j*2+q] += v * v; }
                    if (Ohi) {
                        __nv_bfloat16 hv = __float2bfloat16(v);
                        Ohi[(long)r * KPAD + cc] = hv;
                        Olo[(long)r * KPAD + cc] = __float2bfloat16(v - __bfloat162float(hv));
                    } else if (C2) {
                        if (cc < 87) C[(long)r * 87 + cc] = v;
                        else         C2[(long)r * 6 + (cc - 87)] = v;
                    } else {
                        C[(long)r * Nout + cc] = v;
                        if (Cmir) Cmir[(long)r * Nout + cc] = v;
                    }
                }
            }
        }
    }

    if (doStats) {
        // warp reduce over g-lanes (stride 4, 8, 16 share the same tig)
        #pragma unroll
        for (int t = 0; t < 8; t++) {
            #pragma unroll
            for (int off = 16; off >= 4; off >>= 1) {
                cs[t] += __shfl_down_sync(0xFFFFFFFFu, cs[t], off);
                cq[t] += __shfl_down_sync(0xFFFFFFFFu, cq[t], off);
            }
        }
        float* ssm = (float*)sm;   // reuse staging smem: [64 cols][2]
        __syncthreads();
        if (tid < 128) ssm[tid] = 0.f;
        __syncthreads();
        if (g == 0) {  // lanes 0..3 hold the warp's column sums
            #pragma unroll
            for (int j = 0; j < 4; j++)
                #pragma unroll
                for (int q = 0; q < 2; q++) {
                    int cl = wn * 32 + j * 8 + tig * 2 + q;   // 0..63
                    atomicAdd(&ssm[cl * 2 + 0], cs[j*2+q]);
                    atomicAdd(&ssm[cl * 2 + 1], cq[j*2+q]);
                }
        }
        __syncthreads();
        if (tid < 64) {
            int cc = n0 + tid;
            if (cc < DD) {
                atomicAdd(&g_stats[cc],      ssm[tid * 2 + 0]);
                atomicAdd(&g_stats[DD + cc], ssm[tid * 2 + 1]);
            }
        }
    }
}

// ---------------- misc elementwise kernels ----------------------------------
__global__ void zero_stats_k() {
    int t = threadIdx.x;
    if (t < 2 * DD) g_stats[t] = 0.f;
}

// buf[dst] += relu(h[src] + e)  (one warp per edge, float4)
__global__ void scatter_k(const float* __restrict__ h, const float* __restrict__ e,
                          const int* __restrict__ src, const int* __restrict__ dst,
                          float* __restrict__ buf, int E) {
    int warp = (int)(((long)blockIdx.x * blockDim.x + threadIdx.x) >> 5);
    int lane = threadIdx.x & 31;
    if (warp >= E) return;
    int s = src[warp], t = dst[warp];
    const float4* hr = (const float4*)(h) + (long)s * D4;
    const float4* er = (const float4*)(e) + (long)warp * D4;
    float* br = buf + (long)t * DD;
    for (int i = lane; i < D4; i += 32) {
        float4 hv = hr[i], ev = er[i];
        float v0 = hv.x + ev.x, v1 = hv.y + ev.y, v2 = hv.z + ev.z, v3 = hv.w + ev.w;
        if (v0 > 0.f) atomicAdd(&br[i*4+0], v0);
        if (v1 > 0.f) atomicAdd(&br[i*4+1], v1);
        if (v2 > 0.f) atomicAdd(&br[i*4+2], v2);
        if (v3 > 0.f) atomicAdd(&br[i*4+3], v3);
    }
}

// h = relu(bn(hh)); mirror into buf; optional split output (final layer -> heads)
__global__ void bn_apply_k(const float* __restrict__ hh, const float* __restrict__ gamma,
                           const float* __restrict__ beta, float* __restrict__ h,
                           float* __restrict__ buf,
                           __nv_bfloat16* __restrict__ ohi, __nv_bfloat16* __restrict__ olo,
                           int N) {
    long idx = (long)blockIdx.x * blockDim.x + threadIdx.x;
    if (idx >= (long)N * D4) return;
    int du = (int)(idx % D4);
    long r = idx / D4;
    float invN = 1.f / (float)N;
    float4 x = ((const float4*)hh)[idx];
    float o[4] = {x.x, x.y, x.z, x.w};
    #pragma unroll
    for (int c = 0; c < 4; c++) {
        int d = du * 4 + c;
        float mu  = g_stats[d] * invN;
        float var = g_stats[DD + d] * invN - mu * mu;
        float rstd = rsqrtf(var + 1e-5f);
        float v = (o[c] - mu) * rstd * gamma[d] + beta[d];
        o[c] = fmaxf(v, 0.f);
    }
    float4 res = make_float4(o[0], o[1], o[2], o[3]);
    ((float4*)h)[idx]   = res;
    ((float4*)buf)[idx] = res;
    if (ohi) {
        long base = r * KPAD + du * 4;
        unsigned p01h = pack_bf2(o[0], o[1]), p23h = pack_bf2(o[2], o[3]);
        float l0 = o[0] - __bfloat162float(__float2bfloat16(o[0]));
        float l1 = o[1] - __bfloat162float(__float2bfloat16(o[1]));
        float l2 = o[2] - __bfloat162float(__float2bfloat16(o[2]));
        float l3 = o[3] - __bfloat162float(__float2bfloat16(o[3]));
        *(unsigned*)(ohi + base)     = p01h;
        *(unsigned*)(ohi + base + 2) = p23h;
        *(unsigned*)(olo + base)     = pack_bf2(l0, l1);
        *(unsigned*)(olo + base + 2) = pack_bf2(l2, l3);
    }
}

// ---------------- driver ----------------------------------------------------
static void launch_mma(const __nv_bfloat16* ahi, const __nv_bfloat16* alo,
                       const __nv_bfloat16* whi, const __nv_bfloat16* wlo,
                       const float* bias, const float* addmat,
                       float* C, float* C2, float* Cmir,
                       __nv_bfloat16* ohi, __nv_bfloat16* olo,
                       int M, int Nout, int relu, int stats) {
    dim3 grid((Nout + BN - 1) / BN, (M + BM - 1) / BM);
    mmagemm_k<<<grid, 256, SM_DBL>>>(ahi, alo, whi, wlo, bias, addmat,
                                     C, C2, Cmir, ohi, olo, M, Nout, relu, stats);
}

extern "C" void kernel_launch(void* const* d_in, const int* in_sizes, int n_in,
                              void* d_out, int out_size) {
    const int*   z    = (const int*)  d_in[0];
    const float* chir = (const float*)d_in[1];
    const float* fchg = (const float*)d_in[2];
    const int*   ei   = (const int*)  d_in[3];
    const float* ea   = (const float*)d_in[4];
    const float* emb  = (const float*)d_in[5];
    const float* nw1  = (const float*)d_in[6];
    const float* nb1  = (const float*)d_in[7];
    const float* nw2  = (const float*)d_in[8];
    const float* nb2  = (const float*)d_in[9];
    const float* ew1  = (const float*)d_in[10];
    const float* eb1  = (const float*)d_in[11];
    const float* ew2  = (const float*)d_in[12];
    const float* eb2  = (const float*)d_in[13];
    const float* gw1  = (const float*)d_in[14];
    const float* gb1  = (const float*)d_in[15];
    const float* gw2  = (const float*)d_in[16];
    const float* gb2  = (const float*)d_in[17];
    const float* gam  = (const float*)d_in[18];
    const float* bet  = (const float*)d_in[19];
    const float* ahw  = (const float*)d_in[20];
    const float* ahb  = (const float*)d_in[21];
    const float* chw  = (const float*)d_in[22];
    const float* chb  = (const float*)d_in[23];

    const int N = in_sizes[0];
    const int E = in_sizes[3] / 2;
    const int* src = ei;
    const int* dst = ei + E;

    static int smem_set = 0;
    if (!smem_set) {
        cudaFuncSetAttribute(mmagemm_k, cudaFuncAttributeMaxDynamicSharedMemorySize, SM_DBL);
        smem_set = 1;
    }

    float *pe, *phh, *ph, *pbuf, *phb;
    __nv_bfloat16 *pahi, *palo, *pbhi, *pblo, *pwhi, *pwlo;
    cudaGetSymbolAddress((void**)&pe,   g_e);
    cudaGetSymbolAddress((void**)&phh,  g_tmp);
    cudaGetSymbolAddress((void**)&ph,   g_h);
    cudaGetSymbolAddress((void**)&pbuf, g_buf);
    cudaGetSymbolAddress((void**)&phb,  g_hb);
    cudaGetSymbolAddress((void**)&pahi, g_ahi);
    cudaGetSymbolAddress((void**)&palo, g_alo);
    cudaGetSymbolAddress((void**)&pbhi, g_bhi);
    cudaGetSymbolAddress((void**)&pblo, g_blo);
    cudaGetSymbolAddress((void**)&pwhi, g_whi);
    cudaGetSymbolAddress((void**)&pwlo, g_wlo);

    const long ND = (long)N * DD;
    (void)ND;
    const int WS_BLK = (DD * KPAD + 255) / 256;

    // ---- edge encoder: e = relu(ea @ ew1 + eb1) @ ew2 + eb2 ----
    edge_pre_split_k<<<(unsigned)(((long)E * KP8 + 255) / 256), 256>>>(ea, ew1, eb1, pahi, palo, E);
    wsplit_k<<<WS_BLK, 256>>>(ew2, pwhi, pwlo);
    launch_mma(pahi, palo, pwhi, pwlo, eb2, nullptr,
               pe, nullptr, nullptr, nullptr, nullptr, E, DD, 0, 0);

    // ---- node init: h = emb[z] + relu(na @ nw1 + nb1) @ nw2 + nb2; mirror -> buf ----
    node_pre_split_k<<<(unsigned)(((long)N * KP8 + 255) / 256), 256>>>(
        z, chir, fchg, nw1, nb1, emb, pahi, palo, pbuf, N);
    wsplit_k<<<WS_BLK, 256>>>(nw2, pwhi, pwlo);
    launch_mma(pahi, palo, pwhi, pwlo, nb2, pbuf,
               ph, nullptr, pbuf, nullptr, nullptr, N, DD, 0, 0);

    // ---- 5 GINE layers ----
    for (int l = 0; l < 5; l++) {
        scatter_k<<<(E + 7) / 8, 256>>>(ph, pe, src, dst, pbuf, E);
        // GEMM1: t1 = relu(buf @ W1 + b1) -> split bhi/blo
        split_k<<<(unsigned)(((long)N * KP8 + 255) / 256), 256>>>(pbuf, pahi, palo, N);
        wsplit_k<<<WS_BLK, 256>>>(gw1 + (long)l * DD * DD, pwhi, pwlo);
        launch_mma(pahi, palo, pwhi, pwlo, gb1 + l * DD, nullptr,
                   nullptr, nullptr, nullptr, pbhi, pblo, N, DD, 1, 0);
        // GEMM2: hh = t1 @ W2 + b2 (fp32 out, fused BN stats)
        wsplit_k<<<WS_BLK, 256>>>(gw2 + (long)l * DD * DD, pwhi, pwlo);
        zero_stats_k<<<1, 2 * DD>>>();
        launch_mma(pbhi, pblo, pwhi, pwlo, gb2 + l * DD, nullptr,
                   phh, nullptr, nullptr, nullptr, nullptr, N, DD, 0, 1);
        // batchnorm + relu; mirror into buf; final layer emits split h for heads
        bool last = (l == 4);
        bn_apply_k<<<(unsigned)(((long)N * D4 + 255) / 256), 256>>>(
            phh, gam + l * DD, bet + l * DD, ph, pbuf,
            last ? pbhi : nullptr, last ? pblo : nullptr, N);
    }

    // ---- heads: one 93-col GEMM, epilogue routes to the two output regions ----
    float* out = (float*)d_out;
    hsplit_k<<<(93 * KPAD + 255) / 256, 256>>>(ahw, chw, ahb, chb, pwhi, pwlo);
    launch_mma(pbhi, pblo, pwhi, pwlo, phb, nullptr,
               out, out + (long)N * 87, nullptr, nullptr, nullptr, N, 93, 0, 0);
}